// round 9
// baseline (speedup 1.0000x reference)
#include <cuda_runtime.h>
#include <math.h>
#include <stdint.h>

#define HID   128
#define TIN   512
#define TTOT  514
#define CSIZE 16
#define GRID_N 128     // 8 independent clusters x 16 CTAs
#define NTHR  256

// smem float offsets
#define OFF_BAR 0        // 6 mbarriers (u64) in first 16 floats
#define OFF_W0  16       // layer0: 32 rows x stride 132 = 4224
#define OFF_WR  4240     // layers1-4: 4 x (32 rows x stride 260) = 33280
#define OFF_H   37520    // h buffers [5][2][128 units][4 bat] = 5120
#define OFF_X   42640    // x preload [512][4] = 2048 (+pad)
#define OFF_B   44696    // biases [5][32]
#define OFF_WX  44856    // layer0 input weights [32]
#define OFF_G   44888    // gate exchange 64 float2 = 128 floats
#define OFF_XP  45016    // xpred [2][4]
#define SMEM_BYTES (45056 * 4)

__device__ __forceinline__ float2 ffma2(float w, float2 h, float2 acc) {
    union { float2 f; unsigned long long u; } A, B, C, D;
    A.f = make_float2(w, w); B.f = h; C.f = acc;
    asm("fma.rn.f32x2 %0, %1, %2, %3;" : "=l"(D.u) : "l"(A.u), "l"(B.u), "l"(C.u));
    return D.f;
}
__device__ __forceinline__ float sigm(float v) { return 1.0f / (1.0f + expf(-v)); }
__device__ __forceinline__ float act1(float i, float f, float g, float o, float& c) {
    i = sigm(i); f = sigm(f); g = tanhf(g); o = sigm(o);
    c = f * c + i * g;
    return o * tanhf(c);
}
__device__ __forceinline__ uint32_t mapa_u32(uint32_t a, uint32_t r) {
    uint32_t d; asm("mapa.shared::cluster.u32 %0,%1,%2;" : "=r"(d) : "r"(a), "r"(r)); return d;
}
__device__ __forceinline__ void st_cluster_f2(uint32_t a, float2 v) {
    asm volatile("st.shared::cluster.v2.f32 [%0],{%1,%2};" :: "r"(a), "f"(v.x), "f"(v.y) : "memory");
}
__device__ __forceinline__ void st_cluster_f1(uint32_t a, float v) {
    asm volatile("st.shared::cluster.f32 [%0],%1;" :: "r"(a), "f"(v) : "memory");
}
__device__ __forceinline__ void fence_cluster() {
    asm volatile("fence.acq_rel.cluster;" ::: "memory");
}
__device__ __forceinline__ void mbar_init(uint32_t a, uint32_t n) {
    asm volatile("mbarrier.init.shared.b64 [%0],%1;" :: "r"(a), "r"(n) : "memory");
}
__device__ __forceinline__ void mbar_arrive(uint32_t a) {
    asm volatile("mbarrier.arrive.shared::cluster.b64 _,[%0];" :: "r"(a) : "memory");
}
__device__ __forceinline__ void bar_wait(uint32_t a, uint32_t parity) {
    uint32_t done;
    do {
        asm volatile(
            "{\n\t.reg .pred p;\n\t"
            "mbarrier.try_wait.parity.acquire.cluster.shared::cta.b64 p,[%1],%2;\n\t"
            "selp.b32 %0,1,0,p;\n\t}"
            : "=r"(done) : "r"(a), "r"(parity) : "memory");
    } while (!done);
}

// activation + DSMEM push for layer L
#define ACT_PUSH(L, CST)                                                              \
    if (tid < 16) {                                                                   \
        int u = tid >> 1, pp = tid & 1;                                               \
        float2 gi = sG2[(u*4+0)*2+pp], gf = sG2[(u*4+1)*2+pp];                        \
        float2 gg = sG2[(u*4+2)*2+pp], go = sG2[(u*4+3)*2+pp];                        \
        float2 ho;                                                                    \
        ho.x = act1(gi.x, gf.x, gg.x, go.x, CST.x);                                   \
        ho.y = act1(gi.y, gf.y, gg.y, go.y, CST.y);                                   \
        uint32_t hoff = sbase + (uint32_t)(OFF_H + ((L)*2+par)*512 + (rank*8+u)*4 + pp*2) * 4; \
        uint32_t boff = sbase + (uint32_t)(OFF_BAR*4 + (L)*8);                        \
        _Pragma("unroll")                                                             \
        for (int jj = 0; jj < CSIZE; jj++) st_cluster_f2(mapa_u32(hoff, jj), ho);     \
        fence_cluster();                                                              \
        _Pragma("unroll")                                                             \
        for (int jj = 0; jj < CSIZE; jj++) mbar_arrive(mapa_u32(boff, jj));           \
    }

#define PHASE(L, CST)                                                                 \
    {                                                                                 \
        bar_wait(sbase + (uint32_t)(OFF_BAR*4 + ((L)-1)*8), par);                     \
        float2 acc = make_float2(0.f, 0.f);                                           \
        const float4* w4 = (const float4*)&smem[OFF_WR + ((L)-1)*8320 + r*260 + kq*64]; \
        int lb = (kq < 2) ? ((L)-1) : (L);                                            \
        int pb = (kq < 2) ? par : (par ^ 1);                                          \
        const float* hb = &smem[OFF_H + (lb*2+pb)*512 + (kq&1)*256 + p*2];            \
        _Pragma("unroll")                                                             \
        for (int j = 0; j < 16; j++) {                                                \
            float4 wv = w4[j]; const float* h = hb + j*16;                            \
            acc = ffma2(wv.x, *(const float2*)(h+0),  acc);                           \
            acc = ffma2(wv.y, *(const float2*)(h+4),  acc);                           \
            acc = ffma2(wv.z, *(const float2*)(h+8),  acc);                           \
            acc = ffma2(wv.w, *(const float2*)(h+12), acc);                           \
        }                                                                             \
        acc.x += __shfl_xor_sync(~0u, acc.x, 2); acc.y += __shfl_xor_sync(~0u, acc.y, 2); \
        acc.x += __shfl_xor_sync(~0u, acc.x, 4); acc.y += __shfl_xor_sync(~0u, acc.y, 4); \
        if ((tid & 6) == 0) {                                                         \
            float bb = smem[OFF_B + (L)*32 + r];                                      \
            acc.x += bb; acc.y += bb;                                                 \
            sG2[r*2+p] = acc;                                                         \
        }                                                                             \
        __syncthreads();                                                              \
        ACT_PUSH(L, CST)                                                              \
    }

__global__ void __launch_bounds__(NTHR, 1)
lstm_main(const float* __restrict__ x,    const float* __restrict__ Wih0,
          const float* __restrict__ Wihr, const float* __restrict__ Whh,
          const float* __restrict__ bih,  const float* __restrict__ bhh,
          const float* __restrict__ W1,   const float* __restrict__ b1,
          const float* __restrict__ W2,   const float* __restrict__ b2,
          float* __restrict__ out)
{
    extern __shared__ float smem[];
    const uint32_t sbase = (uint32_t)__cvta_generic_to_shared(smem);
    const int tid = threadIdx.x;
    uint32_t rank_u;
    asm("mov.u32 %0, %%cluster_ctarank;" : "=r"(rank_u));
    const int rank = (int)rank_u;
    const int b0 = (blockIdx.x / CSIZE) * 4;   // batch base of this cluster

    // ---- init: 6 mbarriers (0-4: 256 arrivals; 5: 4 arrivals) ----
    if (tid == 0) {
        for (int l = 0; l < 5; l++) mbar_init(sbase + OFF_BAR*4 + l*8, 256);
        mbar_init(sbase + OFF_BAR*4 + 5*8, 4);
    }
    for (int i = tid; i < 5120; i += NTHR) smem[OFF_H + i] = 0.0f;
    // layer0 weights (hh), row r = u*4+g, stride 132
    for (int i = tid; i < 32 * 128; i += NTHR) {
        int rr_ = i >> 7, k = i & 127, u = rr_ >> 2, g = rr_ & 3;
        smem[OFF_W0 + rr_*132 + k] = Whh[(g*HID + rank*8 + u) * HID + k];
    }
    // layers 1-4 weights [ih | hh], stride 260
    for (int l = 1; l < 5; l++) {
        const float* wih = Wihr + (size_t)(l - 1) * 512 * HID;
        const float* whh = Whh  + (size_t)l * 512 * HID;
        for (int i = tid; i < 32 * 256; i += NTHR) {
            int rr_ = i >> 8, k = i & 255, u = rr_ >> 2, g = rr_ & 3;
            int R = g*HID + rank*8 + u;
            smem[OFF_WR + (l-1)*8320 + rr_*260 + k] =
                (k < 128) ? wih[R*HID + k] : whh[R*HID + k - 128];
        }
    }
    for (int i = tid; i < 160; i += NTHR) {
        int l = i >> 5, rr_ = i & 31, u = rr_ >> 2, g = rr_ & 3;
        int R = l*512 + g*HID + rank*8 + u;
        smem[OFF_B + i] = bih[R] + bhh[R];
    }
    if (tid < 32) {
        int u = tid >> 2, g = tid & 3;
        smem[OFF_WX + tid] = Wih0[g*HID + rank*8 + u];
    }
    for (int i = tid; i < TIN * 4; i += NTHR) {
        int bl = i & 3, t = i >> 2;
        smem[OFF_X + t*4 + bl] = x[(b0 + bl) * TIN + t];
    }
    __syncthreads();
    asm volatile("barrier.cluster.arrive.aligned;" ::: "memory");
    asm volatile("barrier.cluster.wait.aligned;" ::: "memory");

    // compute roles
    const int r  = tid >> 3;         // gate row 0..31 (= u*4 + g)
    const int kq = (tid >> 1) & 3;   // K quarter
    const int p  = tid & 1;          // batch pair
    float2* sG2 = (float2*)(smem + OFF_G);
    float2 cst0 = make_float2(0.f,0.f), cst1 = cst0, cst2 = cst0, cst3 = cst0, cst4 = cst0;

    for (int t = 0; t < TTOT; t++) {
        const int par = t & 1;

        // ---------- phase 0 (layer 0) ----------
        if (t > 0) bar_wait(sbase + OFF_BAR*4 + 4*8, par ^ 1); // h(t-1) ready; sG/sH safe
        float2 xv;
        if (t < TIN) {
            xv = *(const float2*)&smem[OFF_X + t*4 + p*2];
        } else {
            bar_wait(sbase + OFF_BAR*4 + 5*8, t - TIN);        // xpred distributed
            xv = *(const float2*)&smem[OFF_XP + (t - TIN)*4 + p*2];
        }
        {
            float2 acc = make_float2(0.f, 0.f);
            const float4* w4 = (const float4*)&smem[OFF_W0 + r*132 + kq*32];
            const float* hb = &smem[OFF_H + (par ^ 1)*512 + kq*128 + p*2];
            #pragma unroll
            for (int j = 0; j < 8; j++) {
                float4 wv = w4[j]; const float* h = hb + j*16;
                acc = ffma2(wv.x, *(const float2*)(h+0),  acc);
                acc = ffma2(wv.y, *(const float2*)(h+4),  acc);
                acc = ffma2(wv.z, *(const float2*)(h+8),  acc);
                acc = ffma2(wv.w, *(const float2*)(h+12), acc);
            }
            acc.x += __shfl_xor_sync(~0u, acc.x, 2); acc.y += __shfl_xor_sync(~0u, acc.y, 2);
            acc.x += __shfl_xor_sync(~0u, acc.x, 4); acc.y += __shfl_xor_sync(~0u, acc.y, 4);
            if ((tid & 6) == 0) {
                float bb = smem[OFF_B + r];
                acc.x += bb; acc.y += bb;
                acc = ffma2(smem[OFF_WX + r], xv, acc);
                sG2[r*2 + p] = acc;
            }
        }
        __syncthreads();
        ACT_PUSH(0, cst0)

        // ---------- phases 1..4 ----------
        PHASE(1, cst1)
        PHASE(2, cst2)
        PHASE(3, cst3)
        PHASE(4, cst4)

        // ---------- head (rank 0 only, boundary steps; fully cluster-local) ----------
        if (rank == 0 && t >= 511) {
            int m = t - 511;
            bar_wait(sbase + OFF_BAR*4 + 4*8, par);        // h4(t) in local sH
            float* z2 = &smem[OFF_H + (par ^ 1)*512];      // dead h0 slot as scratch
            const float* h4 = &smem[OFF_H + (8 + par)*512];
            {   // z2 = relu(relu(h4^T) @ W1 + b1) : 4 x 128
                int b = tid >> 6, jj = tid & 63;
                float2 acc = *(const float2*)&b1[jj*2];
                for (int k = 0; k < HID; k++) {
                    float zv = fmaxf(h4[k*4 + b], 0.0f);
                    float2 w = *(const float2*)&W1[k*HID + jj*2];
                    acc.x += zv * w.x; acc.y += zv * w.y;
                }
                z2[b*128 + jj*2]     = fmaxf(acc.x, 0.0f);
                z2[b*128 + jj*2 + 1] = fmaxf(acc.y, 0.0f);
            }
            __syncthreads();
            if (tid < 64) {   // out = z2 @ W2 + b2 : 4 x 16
                int b = tid >> 4, oo = tid & 15;
                float s = b2[oo];
                #pragma unroll 8
                for (int j = 0; j < HID; j++) s += z2[b*128 + j] * W2[j*16 + oo];
                if (m == 2) {
                    out[(b0 + b)*18 + 2 + oo] = s;
                } else if (oo == 15) {
                    out[(b0 + b)*18 + m] = s;
                    uint32_t xoff = sbase + (uint32_t)(OFF_XP + m*4 + b) * 4;
                    uint32_t boff = sbase + (uint32_t)(OFF_BAR*4 + 5*8);
                    #pragma unroll
                    for (int jj2 = 0; jj2 < CSIZE; jj2++) st_cluster_f1(mapa_u32(xoff, jj2), s);
                    fence_cluster();
                    #pragma unroll
                    for (int jj2 = 0; jj2 < CSIZE; jj2++) mbar_arrive(mapa_u32(boff, jj2));
                }
            }
            __syncthreads();   // z2 scratch fully consumed before next step
        }
    }

    asm volatile("barrier.cluster.arrive.aligned;" ::: "memory");
    asm volatile("barrier.cluster.wait.aligned;" ::: "memory");
}

extern "C" void kernel_launch(void* const* d_in, const int* in_sizes, int n_in,
                              void* d_out, int out_size) {
    const float* x    = (const float*)d_in[0];
    const float* Wih0 = (const float*)d_in[2];
    const float* Wihr = (const float*)d_in[3];
    const float* Whh  = (const float*)d_in[4];
    const float* bih  = (const float*)d_in[5];
    const float* bhh  = (const float*)d_in[6];
    const float* W1   = (const float*)d_in[7];
    const float* b1   = (const float*)d_in[8];
    const float* W2   = (const float*)d_in[9];
    const float* b2   = (const float*)d_in[10];
    float* out = (float*)d_out;

    static bool attr_set = false;
    if (!attr_set) {
        cudaFuncSetAttribute(lstm_main, cudaFuncAttributeMaxDynamicSharedMemorySize, SMEM_BYTES);
        cudaFuncSetAttribute(lstm_main, cudaFuncAttributeNonPortableClusterSizeAllowed, 1);
        attr_set = true;
    }

    cudaLaunchConfig_t cfg = {};
    cfg.gridDim = dim3(GRID_N, 1, 1);
    cfg.blockDim = dim3(NTHR, 1, 1);
    cfg.dynamicSmemBytes = SMEM_BYTES;
    cfg.stream = 0;
    cudaLaunchAttribute attrs[1];
    attrs[0].id = cudaLaunchAttributeClusterDimension;
    attrs[0].val.clusterDim.x = CSIZE;
    attrs[0].val.clusterDim.y = 1;
    attrs[0].val.clusterDim.z = 1;
    cfg.attrs = attrs;
    cfg.numAttrs = 1;
    cudaLaunchKernelEx(&cfg, lstm_main, x, Wih0, Wihr, Whh, bih, bhh,
                       W1, b1, W2, b2, out);
}

// round 10
// speedup vs baseline: 8.4839x; 8.4839x over previous
#include <cuda_runtime.h>
#include <math.h>
#include <stdint.h>

#define HID   128
#define TIN   512
#define TTOT  514
#define NGROUP 4       // batch groups of 8
#define NTHR  512
#define GRID_N 80      // 4 groups x 5 layers x 4 CTAs
#define CSIZE 4

// smem float offsets
#define OFF_BAR  0        // 1 mbarrier (8 floats reserved)
#define OFF_W    8        // 128 rows x stride 260 (l>=1) / stride 132 (l0)
#define OFF_HOWN 33288    // [2][128][8] = 2048
#define OFF_HBEL 35336    // [128][8] = 1024
#define OFF_G    36360    // [4][128][12] = 6144
#define OFF_X    42504    // [512][8] = 4096 (layer0)
#define OFF_BIAS 46600    // 128
#define OFF_WX   46728    // 128
#define SMEM_BYTES (46864 * 4)

// global scratch
__device__ float g_h[5][TTOT][NGROUP][HID][8];   // inter-layer h (full history)
__device__ float g_xpred[2][NGROUP][8];
__device__ int   g_cnt[NGROUP][5][TTOT];         // inter-layer flags (4 producers)
__device__ int   g_xdone[NGROUP][2];

__global__ void zero_flags_kernel() {
    int i = blockIdx.x * blockDim.x + threadIdx.x;
    if (i < NGROUP * 5 * TTOT) ((int*)g_cnt)[i] = 0;
    if (i < NGROUP * 2) ((int*)g_xdone)[i] = 0;
}

__device__ __forceinline__ int ld_acq(const int* p) {
    int v; asm volatile("ld.acquire.gpu.global.b32 %0,[%1];" : "=r"(v) : "l"(p)); return v;
}
__device__ __forceinline__ void red_rel(int* p) {
    asm volatile("red.release.gpu.global.add.s32 [%0],1;" :: "l"(p));
}
__device__ __forceinline__ float2 ffma2(float w, float2 h, float2 acc) {
    union { float2 f; unsigned long long u; } A, B, C, D;
    A.f = make_float2(w, w); B.f = h; C.f = acc;
    asm("fma.rn.f32x2 %0, %1, %2, %3;" : "=l"(D.u) : "l"(A.u), "l"(B.u), "l"(C.u));
    return D.f;
}
__device__ __forceinline__ float sigm(float v) { return 1.0f / (1.0f + expf(-v)); }
__device__ __forceinline__ float act1(float i, float f, float g, float o, float& c) {
    i = sigm(i); f = sigm(f); g = tanhf(g); o = sigm(o);
    c = f * c + i * g;
    return o * tanhf(c);
}
__device__ __forceinline__ uint32_t mapa_u32(uint32_t a, uint32_t r) {
    uint32_t d; asm("mapa.shared::cluster.u32 %0,%1,%2;" : "=r"(d) : "r"(a), "r"(r)); return d;
}
__device__ __forceinline__ void st_cluster_f2(uint32_t a, float2 v) {
    asm volatile("st.shared::cluster.v2.f32 [%0],{%1,%2};" :: "r"(a), "f"(v.x), "f"(v.y) : "memory");
}
__device__ __forceinline__ void mbar_init(uint32_t a, uint32_t n) {
    asm volatile("mbarrier.init.shared.b64 [%0],%1;" :: "r"(a), "r"(n) : "memory");
}
__device__ __forceinline__ void mbar_arrive(uint32_t a) {
    asm volatile("mbarrier.arrive.shared::cluster.b64 _,[%0];" :: "r"(a) : "memory");
}
__device__ __forceinline__ void bar_wait(uint32_t a, uint32_t parity) {
    uint32_t done;
    do {
        asm volatile(
            "{\n\t.reg .pred p;\n\t"
            "mbarrier.try_wait.parity.acquire.cluster.shared::cta.b64 p,[%1],%2;\n\t"
            "selp.b32 %0,1,0,p;\n\t}"
            : "=r"(done) : "r"(a), "r"(parity) : "memory");
    } while (!done);
}

__global__ void __launch_bounds__(NTHR, 1)
lstm_main(const float* __restrict__ x,    const float* __restrict__ Wih0,
          const float* __restrict__ Wihr, const float* __restrict__ Whh,
          const float* __restrict__ bih,  const float* __restrict__ bhh,
          const float* __restrict__ W1,   const float* __restrict__ b1,
          const float* __restrict__ W2,   const float* __restrict__ b2,
          float* __restrict__ out)
{
    extern __shared__ float smem[];
    const uint32_t sbase = (uint32_t)__cvta_generic_to_shared(smem);
    const int tid   = threadIdx.x;
    const int bid   = blockIdx.x;
    const int rank  = bid & 3;
    const int lg    = bid >> 2;
    const int layer = lg % 5;
    const int group = lg / 5;
    const int b0    = group * 8;

    // ---- init ----
    if (tid == 0) mbar_init(sbase + OFF_BAR * 4, 3);   // 3 peer-elected arrives
    for (int i = tid; i < 2048; i += NTHR) smem[OFF_HOWN + i] = 0.0f;
    if (layer == 0) {
        // W_hh rows (R = g*128 + rank*32 + u), stride 132
        for (int i = tid; i < 128 * 128; i += NTHR) {
            int r = i >> 7, k = i & 127;
            int R = (r >> 5) * HID + rank * 32 + (r & 31);
            smem[OFF_W + r * 132 + k] = Whh[R * HID + k];
        }
        if (tid < 128) {
            int R = (tid >> 5) * HID + rank * 32 + (tid & 31);
            smem[OFF_WX + tid]   = Wih0[R];
            smem[OFF_BIAS + tid] = bih[R] + bhh[R];
        }
        for (int i = tid; i < TIN * 8; i += NTHR) {
            int t = i >> 3, bb = i & 7;
            smem[OFF_X + t * 8 + bb] = x[(b0 + bb) * TIN + t];
        }
    } else {
        const float* wih = Wihr + (size_t)(layer - 1) * 512 * HID;
        const float* whh = Whh  + (size_t)layer * 512 * HID;
        for (int i = tid; i < 128 * 256; i += NTHR) {
            int r = i >> 8, k = i & 255;
            int R = (r >> 5) * HID + rank * 32 + (r & 31);
            smem[OFF_W + r * 260 + k] = (k < 128) ? wih[R * HID + k] : whh[R * HID + k - 128];
        }
        if (tid < 128) {
            int R = layer * 512 + (tid >> 5) * HID + rank * 32 + (tid & 31);
            smem[OFF_BIAS + tid] = bih[R] + bhh[R];
        }
    }
    __syncthreads();
    asm volatile("barrier.cluster.arrive.aligned;" ::: "memory");
    asm volatile("barrier.cluster.wait.aligned;" ::: "memory");

    // roles: p = partial index 0..3; row = gate-row 0..127 (g = row>>5, u = row&31)
    const int p   = tid >> 7;
    const int row = tid & 127;
    const int au  = tid >> 2, abp = tid & 3;   // act roles (tid<128)
    float2 cst = make_float2(0.0f, 0.0f);
    const uint32_t bar = sbase + OFF_BAR * 4;

    for (int t = 0; t < TTOT; t++) {
        const int par = t & 1;
        float2 a0 = make_float2(0.f,0.f), a1 = a0, a2 = a0, a3 = a0;
        if (p == 0) { float bb = smem[OFF_BIAS + row]; a0 = a1 = a2 = a3 = make_float2(bb, bb); }

        if (layer == 0) {
            if (t > 0) bar_wait(bar, (t - 1) & 1);
            // x term (p==0 threads)
            if (p == 0) {
                float2 x01, x23, x45, x67;
                if (t < TIN) {
                    const float2* xp = (const float2*)&smem[OFF_X + t * 8];
                    x01 = xp[0]; x23 = xp[1]; x45 = xp[2]; x67 = xp[3];
                } else {
                    if (tid == 0) { while (ld_acq(&g_xdone[group][t - TIN]) < 1) {} }
                    asm volatile("bar.sync 2, 128;" ::: "memory");
                    const float2* xp = (const float2*)&g_xpred[t - TIN][group][0];
                    x01 = xp[0]; x23 = xp[1]; x45 = xp[2]; x67 = xp[3];
                }
                float wx = smem[OFF_WX + row];
                a0 = ffma2(wx, x01, a0); a1 = ffma2(wx, x23, a1);
                a2 = ffma2(wx, x45, a2); a3 = ffma2(wx, x67, a3);
            }
            // hh over K-quarter p*32
            const float4* w4 = (const float4*)&smem[OFF_W + row * 132 + p * 32];
            const float*  hb = &smem[OFF_HOWN + (par ^ 1) * 1024 + p * 32 * 8];
            #pragma unroll
            for (int j4 = 0; j4 < 8; j4++) {
                float4 wv = w4[j4];
                #pragma unroll
                for (int jj = 0; jj < 4; jj++) {
                    float w = (jj == 0) ? wv.x : (jj == 1) ? wv.y : (jj == 2) ? wv.z : wv.w;
                    const float4* h4 = (const float4*)(hb + (j4 * 4 + jj) * 8);
                    float4 hA = h4[0], hB = h4[1];
                    a0 = ffma2(w, make_float2(hA.x, hA.y), a0);
                    a1 = ffma2(w, make_float2(hA.z, hA.w), a1);
                    a2 = ffma2(w, make_float2(hB.x, hB.y), a2);
                    a3 = ffma2(w, make_float2(hB.z, hB.w), a3);
                }
            }
        } else {
            const int kh = p >> 1, kq2 = p & 1;
            if (kh == 1) {
                // hh half: needs intra-cluster gather of h(t-1)
                if (t > 0) bar_wait(bar, (t - 1) & 1);
            } else {
                // ih half: stage below h(t) from L2
                if (tid == 0) { while (ld_acq(&g_cnt[group][layer - 1][t]) < 4) {} }
                asm volatile("bar.sync 1, 256;" ::: "memory");
                const float4* src = (const float4*)&g_h[layer - 1][t][group][0][0];
                ((float4*)&smem[OFF_HBEL])[tid] = src[tid];
                asm volatile("bar.sync 1, 256;" ::: "memory");
            }
            const float4* w4 = (const float4*)&smem[OFF_W + row * 260 + kh * 128 + kq2 * 64];
            const float*  hb = (kh ? &smem[OFF_HOWN + (par ^ 1) * 1024] : &smem[OFF_HBEL]) + kq2 * 64 * 8;
            #pragma unroll
            for (int j4 = 0; j4 < 16; j4++) {
                float4 wv = w4[j4];
                #pragma unroll
                for (int jj = 0; jj < 4; jj++) {
                    float w = (jj == 0) ? wv.x : (jj == 1) ? wv.y : (jj == 2) ? wv.z : wv.w;
                    const float4* h4 = (const float4*)(hb + (j4 * 4 + jj) * 8);
                    float4 hA = h4[0], hB = h4[1];
                    a0 = ffma2(w, make_float2(hA.x, hA.y), a0);
                    a1 = ffma2(w, make_float2(hA.z, hA.w), a1);
                    a2 = ffma2(w, make_float2(hB.x, hB.y), a2);
                    a3 = ffma2(w, make_float2(hB.z, hB.w), a3);
                }
            }
        }
        // store partials: sG[p][row][12]
        {
            float* gp = &smem[OFF_G + p * 1536 + row * 12];
            *(float4*)gp       = make_float4(a0.x, a0.y, a1.x, a1.y);
            *(float4*)(gp + 4) = make_float4(a2.x, a2.y, a3.x, a3.y);
        }
        __syncthreads();

        // ---- activation + push (tid < 128: unit au=tid>>2, bat-pair abp=tid&3) ----
        if (tid < 128) {
            float2 gt[4];
            #pragma unroll
            for (int g = 0; g < 4; g++) {
                int rr = g * 32 + au;
                float2 s = make_float2(0.f, 0.f);
                #pragma unroll
                for (int q = 0; q < 4; q++) {
                    float2 v = *(const float2*)&smem[OFF_G + q * 1536 + rr * 12 + abp * 2];
                    s.x += v.x; s.y += v.y;
                }
                gt[g] = s;
            }
            float2 ho;
            ho.x = act1(gt[0].x, gt[1].x, gt[2].x, gt[3].x, cst.x);
            ho.y = act1(gt[0].y, gt[1].y, gt[2].y, gt[3].y, cst.y);
            int uo = rank * 32 + au;
            smem[OFF_HOWN + par * 1024 + uo * 8 + abp * 2]     = ho.x;
            smem[OFF_HOWN + par * 1024 + uo * 8 + abp * 2 + 1] = ho.y;
            uint32_t hoff = sbase + (uint32_t)(OFF_HOWN + par * 1024 + uo * 8 + abp * 2) * 4;
            #pragma unroll
            for (int j = 0; j < CSIZE; j++)
                if (j != rank) st_cluster_f2(mapa_u32(hoff, j), ho);
            if (layer < 4)
                *(float2*)&g_h[layer][t][group][uo][abp * 2] = ho;
        }
        __syncthreads();
        if (tid == NTHR - 1) {
            asm volatile("fence.acq_rel.cluster;" ::: "memory");
            #pragma unroll
            for (int j = 0; j < CSIZE; j++)
                if (j != rank) mbar_arrive(mapa_u32(bar, j));
            if (layer < 4) red_rel(&g_cnt[group][layer][t]);
        }

        // ---- head (layer4 rank0 only, boundary steps, cluster-local) ----
        if (layer == 4 && rank == 0 && t >= 511) {
            int m = t - 511;
            bar_wait(bar, t & 1);               // full h4(t) gathered locally
            const float* h4 = &smem[OFF_HOWN + par * 1024];
            float* z2 = &smem[OFF_G];           // scratch [8][128]
            {   // z2 = relu(relu(h4^T) @ W1 + b1); thread: j=tid&127, bh=tid>>7
                int j = tid & 127, bh = tid >> 7;
                float2 acc = make_float2(b1[j], b1[j]);
                for (int k = 0; k < HID; k++) {
                    float2 hv = *(const float2*)&h4[k * 8 + bh * 2];
                    float w = W1[k * HID + j];
                    acc.x += w * fmaxf(hv.x, 0.0f);
                    acc.y += w * fmaxf(hv.y, 0.0f);
                }
                z2[(2 * bh)     * 128 + j] = fmaxf(acc.x, 0.0f);
                z2[(2 * bh + 1) * 128 + j] = fmaxf(acc.y, 0.0f);
            }
            __syncthreads();
            if (tid < 128) {   // out = z2 @ W2 + b2 : 8 x 16
                int b = tid >> 4, oo = tid & 15;
                float s = b2[oo];
                #pragma unroll 8
                for (int k = 0; k < HID; k++) s += z2[b * 128 + k] * W2[k * 16 + oo];
                if (m == 2) {
                    out[(b0 + b) * 18 + 2 + oo] = s;
                } else if (oo == 15) {
                    out[(b0 + b) * 18 + m] = s;
                    g_xpred[m][group][b] = s;
                }
            }
            __syncthreads();
            if (m < 2 && tid == 0) red_rel(&g_xdone[group][m]);
        }
    }

    asm volatile("barrier.cluster.arrive.aligned;" ::: "memory");
    asm volatile("barrier.cluster.wait.aligned;" ::: "memory");
}

extern "C" void kernel_launch(void* const* d_in, const int* in_sizes, int n_in,
                              void* d_out, int out_size) {
    const float* x    = (const float*)d_in[0];
    const float* Wih0 = (const float*)d_in[2];
    const float* Wihr = (const float*)d_in[3];
    const float* Whh  = (const float*)d_in[4];
    const float* bih  = (const float*)d_in[5];
    const float* bhh  = (const float*)d_in[6];
    const float* W1   = (const float*)d_in[7];
    const float* b1   = (const float*)d_in[8];
    const float* W2   = (const float*)d_in[9];
    const float* b2   = (const float*)d_in[10];
    float* out = (float*)d_out;

    static bool attr_set = false;
    if (!attr_set) {
        cudaFuncSetAttribute(lstm_main, cudaFuncAttributeMaxDynamicSharedMemorySize, SMEM_BYTES);
        attr_set = true;
    }

    zero_flags_kernel<<<21, 512>>>();

    cudaLaunchConfig_t cfg = {};
    cfg.gridDim = dim3(GRID_N, 1, 1);
    cfg.blockDim = dim3(NTHR, 1, 1);
    cfg.dynamicSmemBytes = SMEM_BYTES;
    cfg.stream = 0;
    cudaLaunchAttribute attrs[1];
    attrs[0].id = cudaLaunchAttributeClusterDimension;
    attrs[0].val.clusterDim.x = CSIZE;
    attrs[0].val.clusterDim.y = 1;
    attrs[0].val.clusterDim.z = 1;
    cfg.attrs = attrs;
    cfg.numAttrs = 1;
    cudaLaunchKernelEx(&cfg, lstm_main, x, Wih0, Wihr, Whh, bih, bhh,
                       W1, b1, W2, b2, out);
}

// round 11
// speedup vs baseline: 8.9542x; 1.0554x over previous
#include <cuda_runtime.h>
#include <math.h>
#include <stdint.h>

#define HID   128
#define TIN   512
#define TTOT  514
#define NGROUP 4       // batch groups of 8
#define NTHR  512
#define GRID_N 80      // 4 groups x 5 layers x 4 CTAs
#define CSIZE 4

// smem float offsets
#define OFF_BAR  0        // 1 mbarrier (8 floats reserved)
#define OFF_W    8        // 128 rows x stride 260 (l>=1) / stride 132 (l0)
#define OFF_HOWN 33288    // [2][128][8] = 2048
#define OFF_HBEL 35336    // [128][8] = 1024
#define OFF_G    36360    // [4][128][12] = 6144
#define OFF_X    42504    // [512][8] = 4096 (layer0)
#define OFF_BIAS 46600    // 128
#define OFF_WX   46728    // 128
#define SMEM_BYTES (46864 * 4)

// global scratch
__device__ float g_h[5][TTOT][NGROUP][HID][8];   // inter-layer h (full history)
__device__ float g_xpred[2][NGROUP][8];
__device__ int   g_cnt[NGROUP][5][TTOT];         // inter-layer flags (4 producers)
__device__ int   g_xdone[NGROUP][2];

__global__ void zero_flags_kernel() {
    int i = blockIdx.x * blockDim.x + threadIdx.x;
    if (i < NGROUP * 5 * TTOT) ((int*)g_cnt)[i] = 0;
    if (i < NGROUP * 2) ((int*)g_xdone)[i] = 0;
}

__device__ __forceinline__ int ld_acq(const int* p) {
    int v; asm volatile("ld.acquire.gpu.global.b32 %0,[%1];" : "=r"(v) : "l"(p)); return v;
}
__device__ __forceinline__ void red_rel(int* p) {
    asm volatile("red.release.gpu.global.add.s32 [%0],1;" :: "l"(p));
}
__device__ __forceinline__ float2 ffma2(float w, float2 h, float2 acc) {
    union { float2 f; unsigned long long u; } A, B, C, D;
    A.f = make_float2(w, w); B.f = h; C.f = acc;
    asm("fma.rn.f32x2 %0, %1, %2, %3;" : "=l"(D.u) : "l"(A.u), "l"(B.u), "l"(C.u));
    return D.f;
}
// fast activations: MUFU-based, rel err ~1e-6 (budget is 1e-3)
__device__ __forceinline__ float sigm(float v) {
    return __fdividef(1.0f, 1.0f + __expf(-v));
}
__device__ __forceinline__ float tanh_fast(float v) {
    return 1.0f - __fdividef(2.0f, __expf(2.0f * v) + 1.0f);
}
__device__ __forceinline__ float act1(float i, float f, float g, float o, float& c) {
    i = sigm(i); f = sigm(f); g = tanh_fast(g); o = sigm(o);
    c = f * c + i * g;
    return o * tanh_fast(c);
}
__device__ __forceinline__ uint32_t mapa_u32(uint32_t a, uint32_t r) {
    uint32_t d; asm("mapa.shared::cluster.u32 %0,%1,%2;" : "=r"(d) : "r"(a), "r"(r)); return d;
}
__device__ __forceinline__ void st_cluster_f2(uint32_t a, float2 v) {
    asm volatile("st.shared::cluster.v2.f32 [%0],{%1,%2};" :: "r"(a), "f"(v.x), "f"(v.y) : "memory");
}
__device__ __forceinline__ void mbar_init(uint32_t a, uint32_t n) {
    asm volatile("mbarrier.init.shared.b64 [%0],%1;" :: "r"(a), "r"(n) : "memory");
}
// release-scope arrive: carries prior (syncthreads-ordered) DSMEM stores to cluster scope
__device__ __forceinline__ void mbar_arrive_rel(uint32_t a) {
    asm volatile("mbarrier.arrive.release.cluster.shared::cluster.b64 _,[%0];" :: "r"(a) : "memory");
}
__device__ __forceinline__ void bar_wait(uint32_t a, uint32_t parity) {
    uint32_t done;
    do {
        asm volatile(
            "{\n\t.reg .pred p;\n\t"
            "mbarrier.try_wait.parity.acquire.cluster.shared::cta.b64 p,[%1],%2;\n\t"
            "selp.b32 %0,1,0,p;\n\t}"
            : "=r"(done) : "r"(a), "r"(parity) : "memory");
    } while (!done);
}

__global__ void __launch_bounds__(NTHR, 1)
lstm_main(const float* __restrict__ x,    const float* __restrict__ Wih0,
          const float* __restrict__ Wihr, const float* __restrict__ Whh,
          const float* __restrict__ bih,  const float* __restrict__ bhh,
          const float* __restrict__ W1,   const float* __restrict__ b1,
          const float* __restrict__ W2,   const float* __restrict__ b2,
          float* __restrict__ out)
{
    extern __shared__ float smem[];
    const uint32_t sbase = (uint32_t)__cvta_generic_to_shared(smem);
    const int tid   = threadIdx.x;
    const int bid   = blockIdx.x;
    const int rank  = bid & 3;
    const int lg    = bid >> 2;
    const int layer = lg % 5;
    const int group = lg / 5;
    const int b0    = group * 8;

    // ---- init ----
    if (tid == 0) mbar_init(sbase + OFF_BAR * 4, 3);   // 3 peer-elected arrives
    for (int i = tid; i < 2048; i += NTHR) smem[OFF_HOWN + i] = 0.0f;
    if (layer == 0) {
        for (int i = tid; i < 128 * 128; i += NTHR) {
            int r = i >> 7, k = i & 127;
            int R = (r >> 5) * HID + rank * 32 + (r & 31);
            smem[OFF_W + r * 132 + k] = Whh[R * HID + k];
        }
        if (tid < 128) {
            int R = (tid >> 5) * HID + rank * 32 + (tid & 31);
            smem[OFF_WX + tid]   = Wih0[R];
            smem[OFF_BIAS + tid] = bih[R] + bhh[R];
        }
        for (int i = tid; i < TIN * 8; i += NTHR) {
            int t = i >> 3, bb = i & 7;
            smem[OFF_X + t * 8 + bb] = x[(b0 + bb) * TIN + t];
        }
    } else {
        const float* wih = Wihr + (size_t)(layer - 1) * 512 * HID;
        const float* whh = Whh  + (size_t)layer * 512 * HID;
        for (int i = tid; i < 128 * 256; i += NTHR) {
            int r = i >> 8, k = i & 255;
            int R = (r >> 5) * HID + rank * 32 + (r & 31);
            smem[OFF_W + r * 260 + k] = (k < 128) ? wih[R * HID + k] : whh[R * HID + k - 128];
        }
        if (tid < 128) {
            int R = layer * 512 + (tid >> 5) * HID + rank * 32 + (tid & 31);
            smem[OFF_BIAS + tid] = bih[R] + bhh[R];
        }
    }
    __syncthreads();
    asm volatile("barrier.cluster.arrive.aligned;" ::: "memory");
    asm volatile("barrier.cluster.wait.aligned;" ::: "memory");

    // roles
    const int p   = tid >> 7;
    const int row = tid & 127;
    const int au  = tid >> 2, abp = tid & 3;   // act roles (tid<128)
    float2 cst = make_float2(0.0f, 0.0f);
    const uint32_t bar = sbase + OFF_BAR * 4;

    for (int t = 0; t < TTOT; t++) {
        const int par = t & 1;
        float2 a0 = make_float2(0.f,0.f), a1 = a0, a2 = a0, a3 = a0;
        if (p == 0) { float bb = smem[OFF_BIAS + row]; a0 = a1 = a2 = a3 = make_float2(bb, bb); }

        if (layer == 0) {
            if (t > 0) bar_wait(bar, (t - 1) & 1);
            if (p == 0) {
                float2 x01, x23, x45, x67;
                if (t < TIN) {
                    const float2* xp = (const float2*)&smem[OFF_X + t * 8];
                    x01 = xp[0]; x23 = xp[1]; x45 = xp[2]; x67 = xp[3];
                } else {
                    if (tid == 0) { while (ld_acq(&g_xdone[group][t - TIN]) < 1) {} }
                    asm volatile("bar.sync 2, 128;" ::: "memory");
                    const float2* xp = (const float2*)&g_xpred[t - TIN][group][0];
                    x01 = xp[0]; x23 = xp[1]; x45 = xp[2]; x67 = xp[3];
                }
                float wx = smem[OFF_WX + row];
                a0 = ffma2(wx, x01, a0); a1 = ffma2(wx, x23, a1);
                a2 = ffma2(wx, x45, a2); a3 = ffma2(wx, x67, a3);
            }
            const float4* w4 = (const float4*)&smem[OFF_W + row * 132 + p * 32];
            const float*  hb = &smem[OFF_HOWN + (par ^ 1) * 1024 + p * 32 * 8];
            #pragma unroll
            for (int j4 = 0; j4 < 8; j4++) {
                float4 wv = w4[j4];
                #pragma unroll
                for (int jj = 0; jj < 4; jj++) {
                    float w = (jj == 0) ? wv.x : (jj == 1) ? wv.y : (jj == 2) ? wv.z : wv.w;
                    const float4* h4 = (const float4*)(hb + (j4 * 4 + jj) * 8);
                    float4 hA = h4[0], hB = h4[1];
                    a0 = ffma2(w, make_float2(hA.x, hA.y), a0);
                    a1 = ffma2(w, make_float2(hA.z, hA.w), a1);
                    a2 = ffma2(w, make_float2(hB.x, hB.y), a2);
                    a3 = ffma2(w, make_float2(hB.z, hB.w), a3);
                }
            }
        } else {
            const int kh = p >> 1, kq2 = p & 1;
            if (kh == 1) {
                if (t > 0) bar_wait(bar, (t - 1) & 1);
            } else {
                if (tid == 0) { while (ld_acq(&g_cnt[group][layer - 1][t]) < 4) {} }
                asm volatile("bar.sync 1, 256;" ::: "memory");
                const float4* src = (const float4*)&g_h[layer - 1][t][group][0][0];
                ((float4*)&smem[OFF_HBEL])[tid] = src[tid];
                asm volatile("bar.sync 1, 256;" ::: "memory");
            }
            const float4* w4 = (const float4*)&smem[OFF_W + row * 260 + kh * 128 + kq2 * 64];
            const float*  hb = (kh ? &smem[OFF_HOWN + (par ^ 1) * 1024] : &smem[OFF_HBEL]) + kq2 * 64 * 8;
            #pragma unroll
            for (int j4 = 0; j4 < 16; j4++) {
                float4 wv = w4[j4];
                #pragma unroll
                for (int jj = 0; jj < 4; jj++) {
                    float w = (jj == 0) ? wv.x : (jj == 1) ? wv.y : (jj == 2) ? wv.z : wv.w;
                    const float4* h4 = (const float4*)(hb + (j4 * 4 + jj) * 8);
                    float4 hA = h4[0], hB = h4[1];
                    a0 = ffma2(w, make_float2(hA.x, hA.y), a0);
                    a1 = ffma2(w, make_float2(hA.z, hA.w), a1);
                    a2 = ffma2(w, make_float2(hB.x, hB.y), a2);
                    a3 = ffma2(w, make_float2(hB.z, hB.w), a3);
                }
            }
        }
        {
            float* gp = &smem[OFF_G + p * 1536 + row * 12];
            *(float4*)gp       = make_float4(a0.x, a0.y, a1.x, a1.y);
            *(float4*)(gp + 4) = make_float4(a2.x, a2.y, a3.x, a3.y);
        }
        __syncthreads();

        // ---- activation + push ----
        if (tid < 128) {
            float2 gt[4];
            #pragma unroll
            for (int g = 0; g < 4; g++) {
                int rr = g * 32 + au;
                float2 s = make_float2(0.f, 0.f);
                #pragma unroll
                for (int q = 0; q < 4; q++) {
                    float2 v = *(const float2*)&smem[OFF_G + q * 1536 + rr * 12 + abp * 2];
                    s.x += v.x; s.y += v.y;
                }
                gt[g] = s;
            }
            float2 ho;
            ho.x = act1(gt[0].x, gt[1].x, gt[2].x, gt[3].x, cst.x);
            ho.y = act1(gt[0].y, gt[1].y, gt[2].y, gt[3].y, cst.y);
            int uo = rank * 32 + au;
            *(float2*)&smem[OFF_HOWN + par * 1024 + uo * 8 + abp * 2] = ho;
            uint32_t hoff = sbase + (uint32_t)(OFF_HOWN + par * 1024 + uo * 8 + abp * 2) * 4;
            #pragma unroll
            for (int j = 0; j < CSIZE; j++)
                if (j != rank) st_cluster_f2(mapa_u32(hoff, j), ho);
            if (layer < 4)
                *(float2*)&g_h[layer][t][group][uo][abp * 2] = ho;
        }
        __syncthreads();
        if (tid == NTHR - 1) {
            // release-arrive: no cluster fence (avoids per-step CCTL.IVALL / UCGABAR)
            #pragma unroll
            for (int j = 0; j < CSIZE; j++)
                if (j != rank) mbar_arrive_rel(mapa_u32(bar, j));
            if (layer < 4) red_rel(&g_cnt[group][layer][t]);
        }

        // ---- head (layer4 rank0, boundary steps, cluster-local) ----
        if (layer == 4 && rank == 0 && t >= 511) {
            int m = t - 511;
            bar_wait(bar, t & 1);
            const float* h4 = &smem[OFF_HOWN + par * 1024];
            float* z2 = &smem[OFF_G];
            {
                int j = tid & 127, bh = tid >> 7;
                float2 acc = make_float2(b1[j], b1[j]);
                for (int k = 0; k < HID; k++) {
                    float2 hv = *(const float2*)&h4[k * 8 + bh * 2];
                    float w = W1[k * HID + j];
                    acc.x += w * fmaxf(hv.x, 0.0f);
                    acc.y += w * fmaxf(hv.y, 0.0f);
                }
                z2[(2 * bh)     * 128 + j] = fmaxf(acc.x, 0.0f);
                z2[(2 * bh + 1) * 128 + j] = fmaxf(acc.y, 0.0f);
            }
            __syncthreads();
            if (tid < 128) {
                int b = tid >> 4, oo = tid & 15;
                float s = b2[oo];
                #pragma unroll 8
                for (int k = 0; k < HID; k++) s += z2[b * 128 + k] * W2[k * 16 + oo];
                if (m == 2) {
                    out[(b0 + b) * 18 + 2 + oo] = s;
                } else if (oo == 15) {
                    out[(b0 + b) * 18 + m] = s;
                    g_xpred[m][group][b] = s;
                }
            }
            __syncthreads();
            if (m < 2 && tid == 0) red_rel(&g_xdone[group][m]);
        }
    }

    asm volatile("barrier.cluster.arrive.aligned;" ::: "memory");
    asm volatile("barrier.cluster.wait.aligned;" ::: "memory");
}

extern "C" void kernel_launch(void* const* d_in, const int* in_sizes, int n_in,
                              void* d_out, int out_size) {
    const float* x    = (const float*)d_in[0];
    const float* Wih0 = (const float*)d_in[2];
    const float* Wihr = (const float*)d_in[3];
    const float* Whh  = (const float*)d_in[4];
    const float* bih  = (const float*)d_in[5];
    const float* bhh  = (const float*)d_in[6];
    const float* W1   = (const float*)d_in[7];
    const float* b1   = (const float*)d_in[8];
    const float* W2   = (const float*)d_in[9];
    const float* b2   = (const float*)d_in[10];
    float* out = (float*)d_out;

    static bool attr_set = false;
    if (!attr_set) {
        cudaFuncSetAttribute(lstm_main, cudaFuncAttributeMaxDynamicSharedMemorySize, SMEM_BYTES);
        attr_set = true;
    }

    zero_flags_kernel<<<21, 512>>>();

    cudaLaunchConfig_t cfg = {};
    cfg.gridDim = dim3(GRID_N, 1, 1);
    cfg.blockDim = dim3(NTHR, 1, 1);
    cfg.dynamicSmemBytes = SMEM_BYTES;
    cfg.stream = 0;
    cudaLaunchAttribute attrs[1];
    attrs[0].id = cudaLaunchAttributeClusterDimension;
    attrs[0].val.clusterDim.x = CSIZE;
    attrs[0].val.clusterDim.y = 1;
    attrs[0].val.clusterDim.z = 1;
    cfg.attrs = attrs;
    cfg.numAttrs = 1;
    cudaLaunchKernelEx(&cfg, lstm_main, x, Wih0, Wihr, Whh, bih, bhh,
                       W1, b1, W2, b2, out);
}

// round 12
// speedup vs baseline: 11.5253x; 1.2871x over previous
#include <cuda_runtime.h>
#include <math.h>
#include <stdint.h>

#define HID   128
#define TIN   512
#define TTOT  514
#define NGROUP 4       // batch groups of 8
#define NTHR  512
#define GRID_N 80      // 4 groups x 5 layers x 4 CTAs
#define CSIZE 4

// smem float offsets
#define OFF_BAR  0        // 1 mbarrier (8 floats reserved)
#define OFF_W    8        // 128 rows x stride 260 (l>=1) / stride 132 (l0)
#define OFF_HOWN 33288    // [2][128 k][8 bat] = 2048
#define OFF_HBEL 35336    // [128 k][8 bat] = 1024
#define OFF_G    36360    // partials [128 rows][34 float2] = 8704 floats
#define OFF_X    45064    // [512 t][8 bat] = 4096 (layer0)
#define OFF_BIAS 49160    // 128
#define OFF_WX   49288    // 128
#define SMEM_BYTES (49416 * 4)

// global scratch
__device__ float g_h[5][TTOT][NGROUP][HID][8];   // inter-layer h (full history)
__device__ float g_xpred[2][NGROUP][8];
__device__ int   g_cnt[NGROUP][5][TTOT];
__device__ int   g_xdone[NGROUP][2];

__global__ void zero_flags_kernel() {
    int i = blockIdx.x * blockDim.x + threadIdx.x;
    if (i < NGROUP * 5 * TTOT) ((int*)g_cnt)[i] = 0;
    if (i < NGROUP * 2) ((int*)g_xdone)[i] = 0;
}

__device__ __forceinline__ int ld_acq(const int* p) {
    int v; asm volatile("ld.acquire.gpu.global.b32 %0,[%1];" : "=r"(v) : "l"(p)); return v;
}
__device__ __forceinline__ void red_rel(int* p) {
    asm volatile("red.release.gpu.global.add.s32 [%0],1;" :: "l"(p));
}
__device__ __forceinline__ float2 ffma2(float w, float2 h, float2 acc) {
    union { float2 f; unsigned long long u; } A, B, C, D;
    A.f = make_float2(w, w); B.f = h; C.f = acc;
    asm("fma.rn.f32x2 %0, %1, %2, %3;" : "=l"(D.u) : "l"(A.u), "l"(B.u), "l"(C.u));
    return D.f;
}
__device__ __forceinline__ float sigm(float v) {
    return __fdividef(1.0f, 1.0f + __expf(-v));
}
__device__ __forceinline__ float tanh_fast(float v) {
    return 1.0f - __fdividef(2.0f, __expf(2.0f * v) + 1.0f);
}
__device__ __forceinline__ float act1(float i, float f, float g, float o, float& c) {
    i = sigm(i); f = sigm(f); g = tanh_fast(g); o = sigm(o);
    c = f * c + i * g;
    return o * tanh_fast(c);
}
__device__ __forceinline__ uint32_t mapa_u32(uint32_t a, uint32_t r) {
    uint32_t d; asm("mapa.shared::cluster.u32 %0,%1,%2;" : "=r"(d) : "r"(a), "r"(r)); return d;
}
__device__ __forceinline__ void st_cluster_f2(uint32_t a, float2 v) {
    asm volatile("st.shared::cluster.v2.f32 [%0],{%1,%2};" :: "r"(a), "f"(v.x), "f"(v.y) : "memory");
}
__device__ __forceinline__ void mbar_init(uint32_t a, uint32_t n) {
    asm volatile("mbarrier.init.shared.b64 [%0],%1;" :: "r"(a), "r"(n) : "memory");
}
__device__ __forceinline__ void mbar_arrive_rel(uint32_t a) {
    asm volatile("mbarrier.arrive.release.cluster.shared::cluster.b64 _,[%0];" :: "r"(a) : "memory");
}
__device__ __forceinline__ void bar_wait(uint32_t a, uint32_t parity) {
    uint32_t done;
    do {
        asm volatile(
            "{\n\t.reg .pred p;\n\t"
            "mbarrier.try_wait.parity.acquire.cluster.shared::cta.b64 p,[%1],%2;\n\t"
            "selp.b32 %0,1,0,p;\n\t}"
            : "=r"(done) : "r"(a), "r"(parity) : "memory");
    } while (!done);
}

// 4-k inner body: one weight float4 per row-pair, h float4s broadcast
#define GEMV_J4(J4)                                                            \
    {                                                                          \
        float4 wa = wA4[J4], wb = wB4[J4];                                     \
        _Pragma("unroll")                                                      \
        for (int jj = 0; jj < 4; jj++) {                                       \
            float w1v = (jj == 0) ? wa.x : (jj == 1) ? wa.y : (jj == 2) ? wa.z : wa.w; \
            float w2v = (jj == 0) ? wb.x : (jj == 1) ? wb.y : (jj == 2) ? wb.z : wb.w; \
            float4 h0 = h4[((J4) * 4 + jj) * 2];                               \
            float4 h1 = h4[((J4) * 4 + jj) * 2 + 1];                           \
            float2 p01 = make_float2(h0.x, h0.y), p23 = make_float2(h0.z, h0.w); \
            float2 p45 = make_float2(h1.x, h1.y), p67 = make_float2(h1.z, h1.w); \
            aA0 = ffma2(w1v, p01, aA0); aA1 = ffma2(w1v, p23, aA1);            \
            aA2 = ffma2(w1v, p45, aA2); aA3 = ffma2(w1v, p67, aA3);            \
            aB0 = ffma2(w2v, p01, aB0); aB1 = ffma2(w2v, p23, aB1);            \
            aB2 = ffma2(w2v, p45, aB2); aB3 = ffma2(w2v, p67, aB3);            \
        }                                                                      \
    }

__global__ void __launch_bounds__(NTHR, 1)
lstm_main(const float* __restrict__ x,    const float* __restrict__ Wih0,
          const float* __restrict__ Wihr, const float* __restrict__ Whh,
          const float* __restrict__ bih,  const float* __restrict__ bhh,
          const float* __restrict__ W1,   const float* __restrict__ b1,
          const float* __restrict__ W2,   const float* __restrict__ b2,
          float* __restrict__ out)
{
    extern __shared__ float smem[];
    const uint32_t sbase = (uint32_t)__cvta_generic_to_shared(smem);
    const int tid   = threadIdx.x;
    const int bid   = blockIdx.x;
    const int rank  = bid & 3;
    const int lg    = bid >> 2;
    const int layer = lg % 5;
    const int group = lg / 5;
    const int b0    = group * 8;

    // ---- init ----
    if (tid == 0) mbar_init(sbase + OFF_BAR * 4, 3);
    for (int i = tid; i < 2048; i += NTHR) smem[OFF_HOWN + i] = 0.0f;
    if (layer == 0) {
        for (int i = tid; i < 128 * 128; i += NTHR) {
            int r = i >> 7, k = i & 127;
            int R = (r >> 5) * HID + rank * 32 + (r & 31);
            smem[OFF_W + r * 132 + k] = Whh[R * HID + k];
        }
        if (tid < 128) {
            int R = (tid >> 5) * HID + rank * 32 + (tid & 31);
            smem[OFF_WX + tid]   = Wih0[R];
            smem[OFF_BIAS + tid] = bih[R] + bhh[R];
        }
        for (int i = tid; i < TIN * 8; i += NTHR) {
            int t = i >> 3, bb = i & 7;
            smem[OFF_X + t * 8 + bb] = x[(b0 + bb) * TIN + t];
        }
    } else {
        const float* wih = Wihr + (size_t)(layer - 1) * 512 * HID;
        const float* whh = Whh  + (size_t)layer * 512 * HID;
        for (int i = tid; i < 128 * 256; i += NTHR) {
            int r = i >> 8, k = i & 255;
            int R = (r >> 5) * HID + rank * 32 + (r & 31);
            smem[OFF_W + r * 260 + k] = (k < 128) ? wih[R * HID + k] : whh[R * HID + k - 128];
        }
        if (tid < 128) {
            int R = layer * 512 + (tid >> 5) * HID + rank * 32 + (tid & 31);
            smem[OFF_BIAS + tid] = bih[R] + bhh[R];
        }
    }
    __syncthreads();
    asm volatile("barrier.cluster.arrive.aligned;" ::: "memory");
    asm volatile("barrier.cluster.wait.aligned;" ::: "memory");

    // roles: kc = K-eighth, rp = row-pair base (rows rp, rp+64)
    const int kc = tid >> 6;          // 0..7
    const int rp = tid & 63;          // 0..63
    const int au = tid >> 2, abp = tid & 3;   // act roles (tid<128)
    float2 cst = make_float2(0.0f, 0.0f);
    const uint32_t bar = sbase + OFF_BAR * 4;
    float2* sP = (float2*)&smem[OFF_G];       // [row][34] float2 partials

    for (int t = 0; t < TTOT; t++) {
        const int par = t & 1;
        float2 aA0, aA1, aA2, aA3, aB0, aB1, aB2, aB3;
        if (kc == 0) {
            float bA = smem[OFF_BIAS + rp], bB = smem[OFF_BIAS + rp + 64];
            aA0 = aA1 = aA2 = aA3 = make_float2(bA, bA);
            aB0 = aB1 = aB2 = aB3 = make_float2(bB, bB);
        } else {
            aA0 = aA1 = aA2 = aA3 = make_float2(0.f, 0.f);
            aB0 = aB1 = aB2 = aB3 = aA0;
        }

        if (layer == 0) {
            if (t > 0) bar_wait(bar, (t - 1) & 1);
            if (kc == 0) {
                float4 xlo, xhi;
                if (t < TIN) {
                    const float4* xp = (const float4*)&smem[OFF_X + t * 8];
                    xlo = xp[0]; xhi = xp[1];
                } else {
                    if (tid == 0) { while (ld_acq(&g_xdone[group][t - TIN]) < 1) {} }
                    asm volatile("bar.sync 2, 64;" ::: "memory");
                    const float4* xp = (const float4*)&g_xpred[t - TIN][group][0];
                    xlo = xp[0]; xhi = xp[1];
                }
                float wxA = smem[OFF_WX + rp], wxB = smem[OFF_WX + rp + 64];
                float2 q01 = make_float2(xlo.x, xlo.y), q23 = make_float2(xlo.z, xlo.w);
                float2 q45 = make_float2(xhi.x, xhi.y), q67 = make_float2(xhi.z, xhi.w);
                aA0 = ffma2(wxA, q01, aA0); aA1 = ffma2(wxA, q23, aA1);
                aA2 = ffma2(wxA, q45, aA2); aA3 = ffma2(wxA, q67, aA3);
                aB0 = ffma2(wxB, q01, aB0); aB1 = ffma2(wxB, q23, aB1);
                aB2 = ffma2(wxB, q45, aB2); aB3 = ffma2(wxB, q67, aB3);
            }
            const int koff = kc * 16;
            const float4* wA4 = (const float4*)&smem[OFF_W + rp * 132 + koff];
            const float4* wB4 = (const float4*)&smem[OFF_W + (rp + 64) * 132 + koff];
            const float4* h4  = (const float4*)&smem[OFF_HOWN + (par ^ 1) * 1024 + koff * 8];
            #pragma unroll
            for (int j4 = 0; j4 < 4; j4++) GEMV_J4(j4)
        } else {
            const int kh = kc >> 2;
            const int kl = (kc & 3) * 32;
            if (kh) {
                if (t > 0) bar_wait(bar, (t - 1) & 1);
            } else {
                if (tid == 0) { while (ld_acq(&g_cnt[group][layer - 1][t]) < 4) {} }
                asm volatile("bar.sync 1, 256;" ::: "memory");
                ((float4*)&smem[OFF_HBEL])[tid] =
                    ((const float4*)&g_h[layer - 1][t][group][0][0])[tid];
                asm volatile("bar.sync 1, 256;" ::: "memory");
            }
            const float4* wA4 = (const float4*)&smem[OFF_W + rp * 260 + kh * 128 + kl];
            const float4* wB4 = (const float4*)&smem[OFF_W + (rp + 64) * 260 + kh * 128 + kl];
            const float4* h4  = kh
                ? (const float4*)&smem[OFF_HOWN + (par ^ 1) * 1024 + kl * 8]
                : (const float4*)&smem[OFF_HBEL + kl * 8];
            #pragma unroll
            for (int j4 = 0; j4 < 8; j4++) GEMV_J4(j4)
        }

        // store partials: [row][34] float2, slots kc*4 .. kc*4+3
        {
            float2* pp = sP + rp * 34 + kc * 4;
            *(float4*)(pp)     = make_float4(aA0.x, aA0.y, aA1.x, aA1.y);
            *(float4*)(pp + 2) = make_float4(aA2.x, aA2.y, aA3.x, aA3.y);
            float2* pq = pp + 64 * 34;
            *(float4*)(pq)     = make_float4(aB0.x, aB0.y, aB1.x, aB1.y);
            *(float4*)(pq + 2) = make_float4(aB2.x, aB2.y, aB3.x, aB3.y);
        }
        __syncthreads();

        // ---- activation + push ----
        if (tid < 128) {
            float2 gt[4];
            #pragma unroll
            for (int g = 0; g < 4; g++) {
                const float2* pr = sP + (g * 32 + au) * 34 + abp;
                float2 s = pr[0];
                #pragma unroll
                for (int q = 1; q < 8; q++) {
                    float2 v = pr[q * 4];
                    s.x += v.x; s.y += v.y;
                }
                gt[g] = s;
            }
            float2 ho;
            ho.x = act1(gt[0].x, gt[1].x, gt[2].x, gt[3].x, cst.x);
            ho.y = act1(gt[0].y, gt[1].y, gt[2].y, gt[3].y, cst.y);
            int uo = rank * 32 + au;
            *(float2*)&smem[OFF_HOWN + par * 1024 + uo * 8 + abp * 2] = ho;
            uint32_t hoff = sbase + (uint32_t)(OFF_HOWN + par * 1024 + uo * 8 + abp * 2) * 4;
            #pragma unroll
            for (int j = 0; j < CSIZE; j++)
                if (j != rank) st_cluster_f2(mapa_u32(hoff, j), ho);
            if (layer < 4)
                *(float2*)&g_h[layer][t][group][uo][abp * 2] = ho;
        }
        __syncthreads();
        if (tid == NTHR - 1) {
            #pragma unroll
            for (int j = 0; j < CSIZE; j++)
                if (j != rank) mbar_arrive_rel(mapa_u32(bar, j));
            if (layer < 4) red_rel(&g_cnt[group][layer][t]);
        }

        // ---- head (layer4 rank0, boundary steps, cluster-local) ----
        if (layer == 4 && rank == 0 && t >= 511) {
            int m = t - 511;
            bar_wait(bar, t & 1);
            const float* h4h = &smem[OFF_HOWN + par * 1024];
            float* z2 = &smem[OFF_G];
            {
                int j = tid & 127, bh = tid >> 7;
                float2 acc = make_float2(b1[j], b1[j]);
                for (int k = 0; k < HID; k++) {
                    float2 hv = *(const float2*)&h4h[k * 8 + bh * 2];
                    float w = W1[k * HID + j];
                    acc.x += w * fmaxf(hv.x, 0.0f);
                    acc.y += w * fmaxf(hv.y, 0.0f);
                }
                z2[(2 * bh)     * 128 + j] = fmaxf(acc.x, 0.0f);
                z2[(2 * bh + 1) * 128 + j] = fmaxf(acc.y, 0.0f);
            }
            __syncthreads();
            if (tid < 128) {
                int b = tid >> 4, oo = tid & 15;
                float s = b2[oo];
                #pragma unroll 8
                for (int k = 0; k < HID; k++) s += z2[b * 128 + k] * W2[k * 16 + oo];
                if (m == 2) {
                    out[(b0 + b) * 18 + 2 + oo] = s;
                } else if (oo == 15) {
                    out[(b0 + b) * 18 + m] = s;
                    g_xpred[m][group][b] = s;
                }
            }
            __syncthreads();
            if (m < 2 && tid == 0) red_rel(&g_xdone[group][m]);
        }
    }

    asm volatile("barrier.cluster.arrive.aligned;" ::: "memory");
    asm volatile("barrier.cluster.wait.aligned;" ::: "memory");
}

extern "C" void kernel_launch(void* const* d_in, const int* in_sizes, int n_in,
                              void* d_out, int out_size) {
    const float* x    = (const float*)d_in[0];
    const float* Wih0 = (const float*)d_in[2];
    const float* Wihr = (const float*)d_in[3];
    const float* Whh  = (const float*)d_in[4];
    const float* bih  = (const float*)d_in[5];
    const float* bhh  = (const float*)d_in[6];
    const float* W1   = (const float*)d_in[7];
    const float* b1   = (const float*)d_in[8];
    const float* W2   = (const float*)d_in[9];
    const float* b2   = (const float*)d_in[10];
    float* out = (float*)d_out;

    static bool attr_set = false;
    if (!attr_set) {
        cudaFuncSetAttribute(lstm_main, cudaFuncAttributeMaxDynamicSharedMemorySize, SMEM_BYTES);
        attr_set = true;
    }

    zero_flags_kernel<<<21, 512>>>();

    cudaLaunchConfig_t cfg = {};
    cfg.gridDim = dim3(GRID_N, 1, 1);
    cfg.blockDim = dim3(NTHR, 1, 1);
    cfg.dynamicSmemBytes = SMEM_BYTES;
    cfg.stream = 0;
    cudaLaunchAttribute attrs[1];
    attrs[0].id = cudaLaunchAttributeClusterDimension;
    attrs[0].val.clusterDim.x = CSIZE;
    attrs[0].val.clusterDim.y = 1;
    attrs[0].val.clusterDim.z = 1;
    cfg.attrs = attrs;
    cfg.numAttrs = 1;
    cudaLaunchKernelEx(&cfg, lstm_main, x, Wih0, Wihr, Whh, bih, bhh,
                       W1, b1, W2, b2, out);
}

// round 13
// speedup vs baseline: 11.9450x; 1.0364x over previous
#include <cuda_runtime.h>
#include <math.h>
#include <stdint.h>

#define HID   128
#define TIN   512
#define TTOT  514
#define NGROUP 4
#define NTHR  512
#define GRID_N 144     // 4 groups x (1 + 4 hh + 4 ih) clusters x 4 CTAs
#define CSIZE 4

// smem float offsets
#define OFF_BAR  0        // 1 mbarrier
#define OFF_W    8        // 128 rows x stride 132
#define OFF_HH   16904    // hh: HOWN [2][128][8]=2048 ; ih: HBEL [128][8]=1024
#define OFF_G    18952    // partials [128 rows][34 float2] = 8704 floats
#define OFF_PIH  27656    // staged ih sums [128][8] = 1024
#define OFF_X    28680    // layer0 x [512][8] = 4096
#define OFF_BIAS 32776    // 128
#define OFF_WX   32904    // 128
#define SMEM_BYTES (33032 * 4)

// global scratch
__device__ float g_h[4][TTOT][NGROUP][HID][8];         // layers 0..3 publish
__device__ float g_pih[4][TTOT][NGROUP][4][128][8];    // ih partial sums (full history)
__device__ float g_xpred[2][NGROUP][8];
__device__ int   g_cnt[NGROUP][4][TTOT];               // hh layers 0..3 publish (4 ranks)
__device__ int   g_pflag[NGROUP][4][4];                // ih monotone counters [g][L-1][rank]
__device__ int   g_xdone[NGROUP][2];

__global__ void zero_flags_kernel() {
    int i = blockIdx.x * blockDim.x + threadIdx.x;
    if (i < NGROUP * 4 * TTOT) ((int*)g_cnt)[i] = 0;
    if (i < NGROUP * 4 * 4) ((int*)g_pflag)[i] = 0;
    if (i < NGROUP * 2) ((int*)g_xdone)[i] = 0;
}

__device__ __forceinline__ int ld_acq(const int* p) {
    int v; asm volatile("ld.acquire.gpu.global.b32 %0,[%1];" : "=r"(v) : "l"(p)); return v;
}
__device__ __forceinline__ void red_rel(int* p) {
    asm volatile("red.release.gpu.global.add.s32 [%0],1;" :: "l"(p));
}
__device__ __forceinline__ float2 ffma2(float w, float2 h, float2 acc) {
    union { float2 f; unsigned long long u; } A, B, C, D;
    A.f = make_float2(w, w); B.f = h; C.f = acc;
    asm("fma.rn.f32x2 %0, %1, %2, %3;" : "=l"(D.u) : "l"(A.u), "l"(B.u), "l"(C.u));
    return D.f;
}
__device__ __forceinline__ float sigm(float v) {
    return __fdividef(1.0f, 1.0f + __expf(-v));
}
__device__ __forceinline__ float tanh_fast(float v) {
    return 1.0f - __fdividef(2.0f, __expf(2.0f * v) + 1.0f);
}
__device__ __forceinline__ float act1(float i, float f, float g, float o, float& c) {
    i = sigm(i); f = sigm(f); g = tanh_fast(g); o = sigm(o);
    c = f * c + i * g;
    return o * tanh_fast(c);
}
__device__ __forceinline__ uint32_t mapa_u32(uint32_t a, uint32_t r) {
    uint32_t d; asm("mapa.shared::cluster.u32 %0,%1,%2;" : "=r"(d) : "r"(a), "r"(r)); return d;
}
__device__ __forceinline__ void st_cluster_f2(uint32_t a, float2 v) {
    asm volatile("st.shared::cluster.v2.f32 [%0],{%1,%2};" :: "r"(a), "f"(v.x), "f"(v.y) : "memory");
}
__device__ __forceinline__ void mbar_init(uint32_t a, uint32_t n) {
    asm volatile("mbarrier.init.shared.b64 [%0],%1;" :: "r"(a), "r"(n) : "memory");
}
__device__ __forceinline__ void mbar_arrive_rel(uint32_t a) {
    asm volatile("mbarrier.arrive.release.cluster.shared::cluster.b64 _,[%0];" :: "r"(a) : "memory");
}
__device__ __forceinline__ void bar_wait(uint32_t a, uint32_t parity) {
    uint32_t done;
    do {
        asm volatile(
            "{\n\t.reg .pred p;\n\t"
            "mbarrier.try_wait.parity.acquire.cluster.shared::cta.b64 p,[%1],%2;\n\t"
            "selp.b32 %0,1,0,p;\n\t}"
            : "=r"(done) : "r"(a), "r"(parity) : "memory");
    } while (!done);
}

// 4-k inner body (from R12): one weight float4 per row-pair, broadcast h
#define GEMV_J4(J4)                                                            \
    {                                                                          \
        float4 wa = wA4[J4], wb = wB4[J4];                                     \
        _Pragma("unroll")                                                      \
        for (int jj = 0; jj < 4; jj++) {                                       \
            float w1v = (jj == 0) ? wa.x : (jj == 1) ? wa.y : (jj == 2) ? wa.z : wa.w; \
            float w2v = (jj == 0) ? wb.x : (jj == 1) ? wb.y : (jj == 2) ? wb.z : wb.w; \
            float4 h0 = h4[((J4) * 4 + jj) * 2];                               \
            float4 h1 = h4[((J4) * 4 + jj) * 2 + 1];                           \
            float2 p01 = make_float2(h0.x, h0.y), p23 = make_float2(h0.z, h0.w); \
            float2 p45 = make_float2(h1.x, h1.y), p67 = make_float2(h1.z, h1.w); \
            aA0 = ffma2(w1v, p01, aA0); aA1 = ffma2(w1v, p23, aA1);            \
            aA2 = ffma2(w1v, p45, aA2); aA3 = ffma2(w1v, p67, aA3);            \
            aB0 = ffma2(w2v, p01, aB0); aB1 = ffma2(w2v, p23, aB1);            \
            aB2 = ffma2(w2v, p45, aB2); aB3 = ffma2(w2v, p67, aB3);            \
        }                                                                      \
    }

__global__ void __launch_bounds__(NTHR, 1)
lstm_main(const float* __restrict__ x,    const float* __restrict__ Wih0,
          const float* __restrict__ Wihr, const float* __restrict__ Whh,
          const float* __restrict__ bih,  const float* __restrict__ bhh,
          const float* __restrict__ W1,   const float* __restrict__ b1,
          const float* __restrict__ W2,   const float* __restrict__ b2,
          float* __restrict__ out)
{
    extern __shared__ float smem[];
    const uint32_t sbase = (uint32_t)__cvta_generic_to_shared(smem);
    const int tid  = threadIdx.x;
    const int bid  = blockIdx.x;
    const int rank = bid & 3;
    const int cid  = bid >> 2;
    const int group = cid / 9;
    const int c     = cid % 9;
    const bool is_ih = (c >= 5);
    const int layer  = is_ih ? (c - 4) : c;    // hh: 0..4 ; ih: 1..4
    const int b0 = group * 8;

    // ---- weight staging (both roles), rows r=0..127 -> R=(r>>5)*128+rank*32+(r&31)
    {
        const float* wsrc = is_ih ? (Wihr + (size_t)(layer - 1) * 512 * HID)
                                  : (Whh + (size_t)layer * 512 * HID);
        for (int i = tid; i < 128 * 128; i += NTHR) {
            int r = i >> 7, k = i & 127;
            int R = (r >> 5) * HID + rank * 32 + (r & 31);
            smem[OFF_W + r * 132 + k] = wsrc[R * HID + k];
        }
    }
    if (!is_ih) {
        if (tid == 0) mbar_init(sbase + OFF_BAR * 4, 3);
        for (int i = tid; i < 2048; i += NTHR) smem[OFF_HH + i] = 0.0f;
        if (tid < 128) {
            int R = layer * 512 + (tid >> 5) * HID + rank * 32 + (tid & 31);
            smem[OFF_BIAS + tid] = bih[R] + bhh[R];
            if (layer == 0) smem[OFF_WX + tid] = Wih0[R - 0 * 512];
        }
        if (layer == 0)
            for (int i = tid; i < TIN * 8; i += NTHR) {
                int t = i >> 3, bb = i & 7;
                smem[OFF_X + t * 8 + bb] = x[(b0 + bb) * TIN + t];
            }
    }
    __syncthreads();
    asm volatile("barrier.cluster.arrive.aligned;" ::: "memory");
    asm volatile("barrier.cluster.wait.aligned;" ::: "memory");

    const int kc = tid >> 6;          // K-eighth (16 k)
    const int rp = tid & 63;          // rows rp, rp+64
    const int au = tid >> 2, abp = tid & 3;
    const uint32_t bar = sbase + OFF_BAR * 4;
    float2* sP = (float2*)&smem[OFF_G];

    if (is_ih) {
        // ================= ih CTA: W_ih * h_below, publish sums =================
        for (int t = 0; t < TTOT; t++) {
            const int* pc = &g_cnt[group][layer - 1][t];
            while (ld_acq(pc) < 4) {}
            if (tid < 256)
                ((float4*)&smem[OFF_HH])[tid] =
                    ((const float4*)&g_h[layer - 1][t][group][0][0])[tid];
            __syncthreads();
            float2 aA0, aA1, aA2, aA3, aB0, aB1, aB2, aB3;
            aA0 = aA1 = aA2 = aA3 = make_float2(0.f, 0.f);
            aB0 = aB1 = aB2 = aB3 = aA0;
            const float4* wA4 = (const float4*)&smem[OFF_W + rp * 132 + kc * 16];
            const float4* wB4 = (const float4*)&smem[OFF_W + (rp + 64) * 132 + kc * 16];
            const float4* h4  = (const float4*)&smem[OFF_HH + kc * 16 * 8];
            #pragma unroll
            for (int j4 = 0; j4 < 4; j4++) GEMV_J4(j4)
            {
                float2* pp = sP + rp * 34 + kc * 4;
                *(float4*)(pp)     = make_float4(aA0.x, aA0.y, aA1.x, aA1.y);
                *(float4*)(pp + 2) = make_float4(aA2.x, aA2.y, aA3.x, aA3.y);
                float2* pq = pp + 64 * 34;
                *(float4*)(pq)     = make_float4(aB0.x, aB0.y, aB1.x, aB1.y);
                *(float4*)(pq + 2) = make_float4(aB2.x, aB2.y, aB3.x, aB3.y);
            }
            __syncthreads();
            {   // reduce 8 partials and publish: row = tid>>2, slot = tid&3
                int row = tid >> 2, slot = tid & 3;
                const float2* pr = sP + row * 34 + slot;
                float2 s = pr[0];
                #pragma unroll
                for (int q = 1; q < 8; q++) { float2 v = pr[q * 4]; s.x += v.x; s.y += v.y; }
                *(float2*)&g_pih[layer - 1][t][group][rank][row][slot * 2] = s;
            }
            __syncthreads();
            if (tid == 0) red_rel(&g_pflag[group][layer - 1][rank]);
        }
        return;
    }

    // ================= hh CTA (recurrent loop + act + head) =================
    float2 cst = make_float2(0.0f, 0.0f);
    for (int t = 0; t < TTOT; t++) {
        const int par = t & 1;

        // prefetch ih partial sums (slack path) before the own-h wait
        float4 pih = make_float4(0.f, 0.f, 0.f, 0.f);
        if (layer > 0) {
            const int* pf = &g_pflag[group][layer - 1][rank];
            while (ld_acq(pf) < t + 1) {}
            if (tid < 256)
                pih = ((const float4*)&g_pih[layer - 1][t][group][rank][0][0])[tid];
        }

        float2 aA0, aA1, aA2, aA3, aB0, aB1, aB2, aB3;
        if (kc == 0) {
            float bA = smem[OFF_BIAS + rp], bB = smem[OFF_BIAS + rp + 64];
            aA0 = aA1 = aA2 = aA3 = make_float2(bA, bA);
            aB0 = aB1 = aB2 = aB3 = make_float2(bB, bB);
        } else {
            aA0 = aA1 = aA2 = aA3 = make_float2(0.f, 0.f);
            aB0 = aB1 = aB2 = aB3 = aA0;
        }

        if (layer == 0 && kc == 0) {
            float4 xlo, xhi;
            if (t < TIN) {
                const float4* xp = (const float4*)&smem[OFF_X + t * 8];
                xlo = xp[0]; xhi = xp[1];
            } else {
                if (tid == 0) { while (ld_acq(&g_xdone[group][t - TIN]) < 1) {} }
                asm volatile("bar.sync 2, 64;" ::: "memory");
                const float4* xp = (const float4*)&g_xpred[t - TIN][group][0];
                xlo = xp[0]; xhi = xp[1];
            }
            float wxA = smem[OFF_WX + rp], wxB = smem[OFF_WX + rp + 64];
            float2 q01 = make_float2(xlo.x, xlo.y), q23 = make_float2(xlo.z, xlo.w);
            float2 q45 = make_float2(xhi.x, xhi.y), q67 = make_float2(xhi.z, xhi.w);
            aA0 = ffma2(wxA, q01, aA0); aA1 = ffma2(wxA, q23, aA1);
            aA2 = ffma2(wxA, q45, aA2); aA3 = ffma2(wxA, q67, aA3);
            aB0 = ffma2(wxB, q01, aB0); aB1 = ffma2(wxB, q23, aB1);
            aB2 = ffma2(wxB, q45, aB2); aB3 = ffma2(wxB, q67, aB3);
        }

        if (t > 0) bar_wait(bar, (t - 1) & 1);

        {
            const float4* wA4 = (const float4*)&smem[OFF_W + rp * 132 + kc * 16];
            const float4* wB4 = (const float4*)&smem[OFF_W + (rp + 64) * 132 + kc * 16];
            const float4* h4  = (const float4*)&smem[OFF_HH + (par ^ 1) * 1024 + kc * 16 * 8];
            #pragma unroll
            for (int j4 = 0; j4 < 4; j4++) GEMV_J4(j4)
        }
        {
            float2* pp = sP + rp * 34 + kc * 4;
            *(float4*)(pp)     = make_float4(aA0.x, aA0.y, aA1.x, aA1.y);
            *(float4*)(pp + 2) = make_float4(aA2.x, aA2.y, aA3.x, aA3.y);
            float2* pq = pp + 64 * 34;
            *(float4*)(pq)     = make_float4(aB0.x, aB0.y, aB1.x, aB1.y);
            *(float4*)(pq + 2) = make_float4(aB2.x, aB2.y, aB3.x, aB3.y);
        }
        if (layer > 0 && tid < 256) ((float4*)&smem[OFF_PIH])[tid] = pih;
        __syncthreads();

        // ---- act + push ----
        if (tid < 128) {
            float2 gt[4];
            #pragma unroll
            for (int g = 0; g < 4; g++) {
                int row = g * 32 + au;
                const float2* pr = sP + row * 34 + abp;
                float2 s = pr[0];
                #pragma unroll
                for (int q = 1; q < 8; q++) { float2 v = pr[q * 4]; s.x += v.x; s.y += v.y; }
                if (layer > 0) {
                    float2 v = *(const float2*)&smem[OFF_PIH + row * 8 + abp * 2];
                    s.x += v.x; s.y += v.y;
                }
                gt[g] = s;
            }
            float2 ho;
            ho.x = act1(gt[0].x, gt[1].x, gt[2].x, gt[3].x, cst.x);
            ho.y = act1(gt[0].y, gt[1].y, gt[2].y, gt[3].y, cst.y);
            int uo = rank * 32 + au;
            *(float2*)&smem[OFF_HH + par * 1024 + uo * 8 + abp * 2] = ho;
            uint32_t hoff = sbase + (uint32_t)(OFF_HH + par * 1024 + uo * 8 + abp * 2) * 4;
            #pragma unroll
            for (int j = 0; j < CSIZE; j++)
                if (j != rank) st_cluster_f2(mapa_u32(hoff, j), ho);
            if (layer < 4)
                *(float2*)&g_h[layer][t][group][uo][abp * 2] = ho;
        }
        __syncthreads();
        if (tid == NTHR - 1) {
            #pragma unroll
            for (int j = 0; j < CSIZE; j++)
                if (j != rank) mbar_arrive_rel(mapa_u32(bar, j));
            if (layer < 4) red_rel(&g_cnt[group][layer][t]);
        }

        // ---- head (layer4 rank0, boundary steps) ----
        if (layer == 4 && rank == 0 && t >= 511) {
            int m = t - 511;
            bar_wait(bar, t & 1);
            const float* h4h = &smem[OFF_HH + par * 1024];
            float* z2 = &smem[OFF_G];
            {
                int j = tid & 127, bh = tid >> 7;
                float2 acc = make_float2(b1[j], b1[j]);
                for (int k = 0; k < HID; k++) {
                    float2 hv = *(const float2*)&h4h[k * 8 + bh * 2];
                    float w = W1[k * HID + j];
                    acc.x += w * fmaxf(hv.x, 0.0f);
                    acc.y += w * fmaxf(hv.y, 0.0f);
                }
                z2[(2 * bh)     * 128 + j] = fmaxf(acc.x, 0.0f);
                z2[(2 * bh + 1) * 128 + j] = fmaxf(acc.y, 0.0f);
            }
            __syncthreads();
            if (tid < 128) {
                int b = tid >> 4, oo = tid & 15;
                float s = b2[oo];
                #pragma unroll 8
                for (int k = 0; k < HID; k++) s += z2[b * 128 + k] * W2[k * 16 + oo];
                if (m == 2) {
                    out[(b0 + b) * 18 + 2 + oo] = s;
                } else if (oo == 15) {
                    out[(b0 + b) * 18 + m] = s;
                    g_xpred[m][group][b] = s;
                }
            }
            __syncthreads();
            if (m < 2 && tid == 0) red_rel(&g_xdone[group][m]);
        }
    }

    asm volatile("barrier.cluster.arrive.aligned;" ::: "memory");
    asm volatile("barrier.cluster.wait.aligned;" ::: "memory");
}

extern "C" void kernel_launch(void* const* d_in, const int* in_sizes, int n_in,
                              void* d_out, int out_size) {
    const float* x    = (const float*)d_in[0];
    const float* Wih0 = (const float*)d_in[2];
    const float* Wihr = (const float*)d_in[3];
    const float* Whh  = (const float*)d_in[4];
    const float* bih  = (const float*)d_in[5];
    const float* bhh  = (const float*)d_in[6];
    const float* W1   = (const float*)d_in[7];
    const float* b1   = (const float*)d_in[8];
    const float* W2   = (const float*)d_in[9];
    const float* b2   = (const float*)d_in[10];
    float* out = (float*)d_out;

    static bool attr_set = false;
    if (!attr_set) {
        cudaFuncSetAttribute(lstm_main, cudaFuncAttributeMaxDynamicSharedMemorySize, SMEM_BYTES);
        attr_set = true;
    }

    zero_flags_kernel<<<17, 512>>>();

    cudaLaunchConfig_t cfg = {};
    cfg.gridDim = dim3(GRID_N, 1, 1);
    cfg.blockDim = dim3(NTHR, 1, 1);
    cfg.dynamicSmemBytes = SMEM_BYTES;
    cfg.stream = 0;
    cudaLaunchAttribute attrs[1];
    attrs[0].id = cudaLaunchAttributeClusterDimension;
    attrs[0].val.clusterDim.x = CSIZE;
    attrs[0].val.clusterDim.y = 1;
    attrs[0].val.clusterDim.z = 1;
    cfg.attrs = attrs;
    cfg.numAttrs = 1;
    cudaLaunchKernelEx(&cfg, lstm_main, x, Wih0, Wihr, Whh, bih, bhh,
                       W1, b1, W2, b2, out);
}